// round 15
// baseline (speedup 1.0000x reference)
#include <cuda_runtime.h>
#include <mma.h>
#include <math.h>
#include <stdint.h>

using namespace nvcuda;

#define EMBED   256
#define PAIRS   15
#define TOKENS  16384            // 32 * 512
#define KPAIR   512              // 2 * EMBED
#define KFINAL  3840             // 15 * 256

#define BM 128
#define BN 128
#define BK 32
#define LDA 36                   // 32 + 4 pad floats (144B rows: conflict-free ldmatrix)
#define LDB 36                   // BT tile rows: 32 k-floats + 4 pad (same geometry as A)
#define LDC 136
#define NTH 256

#define A_ST (BM * LDA)          // 4608 floats / stage
#define B_ST (BN * LDB)          // 4608 floats / stage (128 n-rows x 36)
#define SMEM_FLOATS (2 * A_ST + 2 * B_ST)   // 18432 fl = 73728 B
#define SMEM_BYTES  (SMEM_FLOATS * 4 + 64)  // + s_plist area

// ---- global scratch (allocation-free) ----
__device__ float g_H  [(size_t)PAIRS * TOKENS * EMBED];  // tanh outputs, tf32-RN-rounded
__device__ float g_WpT[(size_t)PAIRS * EMBED * KPAIR];   // W_pair^T [p][n][k], tf32-RN-rounded
__device__ float g_WfT[(size_t)EMBED * KFINAL];          // W_final^T [n][k], tf32-RN-rounded

__constant__ int c_PI[PAIRS] = {0,0,0,0,0,1,1,1,1,2,2,2,3,3,4};
__constant__ int c_PJ[PAIRS] = {1,2,3,4,5,2,3,4,5,3,4,5,4,5,5};

__device__ __forceinline__ uint32_t smem_u32(const void* p) {
    uint32_t a;
    asm("{ .reg .u64 t; cvta.to.shared.u64 t, %1; cvt.u32.u64 %0, t; }" : "=r"(a) : "l"(p));
    return a;
}
#define CP16(dst, src) \
    asm volatile("cp.async.cg.shared.global [%0], [%1], 16;" :: "r"(dst), "l"(src) : "memory")
#define CP_COMMIT()  asm volatile("cp.async.commit_group;" ::: "memory")
#define CP_WAIT0()   asm volatile("cp.async.wait_group 0;" ::: "memory")

#define CVT4(dst, v)                                   \
    do {                                               \
        (dst)[0] = wmma::__float_to_tf32((v).x);       \
        (dst)[1] = wmma::__float_to_tf32((v).y);       \
        (dst)[2] = wmma::__float_to_tf32((v).z);       \
        (dst)[3] = wmma::__float_to_tf32((v).w);       \
    } while (0)

// ---------------------------------------------------------------------------
// Pre-pass: transpose + tf32-RN-round weights. z<15: W_pair pair z (skipped if
// inactive); z==15: W_final. grid = (KFINAL/32, EMBED/32, 16).
// ---------------------------------------------------------------------------
__global__ void __launch_bounds__(NTH)
transpose_round(const float* __restrict__ Wp, const float* __restrict__ Wf,
                const int* __restrict__ NAS)
{
    __shared__ float tile[32][33];
    const int z  = blockIdx.z;
    const int kx = blockIdx.x, ny = blockIdx.y;
    const int tx = threadIdx.x & 31, ty = threadIdx.x >> 5;

    const float* src;
    float*       dst;
    int K;
    if (z < PAIRS) {
        if (kx >= KPAIR / 32) return;
        const int fi = c_PI[z], fj = c_PJ[z];
        if (((fi < 2) ? 1 : NAS[fi]) * ((fj < 2) ? 1 : NAS[fj]) == 0) return;
        src = Wp + (size_t)z * KPAIR * EMBED;
        dst = g_WpT + (size_t)z * EMBED * KPAIR;
        K = KPAIR;
    } else {
        src = Wf;
        dst = g_WfT;
        K = KFINAL;
    }
    #pragma unroll
    for (int r = ty; r < 32; r += 8)
        tile[r][tx] = src[(size_t)(kx * 32 + r) * EMBED + ny * 32 + tx];
    __syncthreads();
    #pragma unroll
    for (int r = ty; r < 32; r += 8)
        dst[(size_t)(ny * 32 + r) * K + kx * 32 + tx] = wmma::__float_to_tf32(tile[tx][r]);
}

// ---------------------------------------------------------------------------
// Warp-tile compute: 64x32 per warp via ldmatrix (A and B) + mma.m16n8k8 tf32.
// B lives transposed in smem: BT[n][k] rows of 32 tf32 (+4 pad).
//   per kk8: 4x ldmatrix.x4 (A) + 2x ldmatrix.x4 (B) + 16 MMA.
//   x4 reg order (B): {b0 oct0, b1 oct0, b0 oct1, b1 oct1}.
// ---------------------------------------------------------------------------
#define COMPUTE_STAGE(aBaseU32, bBaseU32)                                                 \
    do {                                                                                  \
        _Pragma("unroll")                                                                 \
        for (int kk8 = 0; kk8 < 4; kk8++) {                                               \
            const int kk = kk8 * 8;                                                       \
            uint32_t a[4][4];                                                             \
            _Pragma("unroll")                                                             \
            for (int m = 0; m < 4; m++) {                                                 \
                uint32_t ad = (aBaseU32) + (uint32_t)((m * 16 * LDA + kk) * 4);           \
                asm volatile(                                                             \
                    "ldmatrix.sync.aligned.m8n8.x4.shared.b16 {%0,%1,%2,%3}, [%4];"       \
                    : "=r"(a[m][0]), "=r"(a[m][1]), "=r"(a[m][2]), "=r"(a[m][3])          \
                    : "r"(ad));                                                           \
            }                                                                             \
            uint32_t b[2][4];                                                             \
            _Pragma("unroll")                                                             \
            for (int g = 0; g < 2; g++) {                                                 \
                uint32_t bd = (bBaseU32) + (uint32_t)((g * 16 * LDB + kk) * 4);           \
                asm volatile(                                                             \
                    "ldmatrix.sync.aligned.m8n8.x4.shared.b16 {%0,%1,%2,%3}, [%4];"       \
                    : "=r"(b[g][0]), "=r"(b[g][1]), "=r"(b[g][2]), "=r"(b[g][3])          \
                    : "r"(bd));                                                           \
            }                                                                             \
            _Pragma("unroll")                                                             \
            for (int n = 0; n < 4; n++) {                                                 \
                uint32_t b0 = b[n >> 1][(n & 1) * 2];                                     \
                uint32_t b1 = b[n >> 1][(n & 1) * 2 + 1];                                 \
                _Pragma("unroll")                                                         \
                for (int m = 0; m < 4; m++)                                               \
                    asm volatile(                                                         \
                        "mma.sync.aligned.m16n8k8.row.col.f32.tf32.tf32.f32 "             \
                        "{%0,%1,%2,%3}, {%4,%5,%6,%7}, {%8,%9}, {%0,%1,%2,%3};"           \
                        : "+f"(c[m][n][0]), "+f"(c[m][n][1]),                             \
                          "+f"(c[m][n][2]), "+f"(c[m][n][3])                              \
                        : "r"(a[m][0]), "r"(a[m][1]), "r"(a[m][2]), "r"(a[m][3]),         \
                          "r"(b0), "r"(b1));                                              \
            }                                                                             \
        }                                                                                 \
    } while (0)

// Store this warp's 64x32 C tile into Cs (64-row half staging), from c fragments.
#define STORE_C_HALF(Cs_)                                                                 \
    do {                                                                                  \
        _Pragma("unroll")                                                                 \
        for (int m = 0; m < 4; m++) {                                                     \
            _Pragma("unroll")                                                             \
            for (int n = 0; n < 4; n++) {                                                 \
                int r0  = m * 16 + lg;                                                    \
                int col = wn * 32 + n * 8 + 2 * lt;                                       \
                *(float2*)((Cs_) + r0 * LDC + col)       = make_float2(c[m][n][0], c[m][n][1]); \
                *(float2*)((Cs_) + (r0 + 8) * LDC + col) = make_float2(c[m][n][2], c[m][n][3]); \
            }                                                                             \
        }                                                                                 \
    } while (0)

// B ldmatrix per-lane address offset (within a BT tile at wn*32):
//   row = (lane&7) + ((lane>>4)&1)*8, colword = ((lane>>3)&1)*4

// ---------------------------------------------------------------------------
// Kernel 1: H[p] = tf32rn( tanh(concat(F_i,F_j) @ W_pair[p] + b_pair[p]) )
// ---------------------------------------------------------------------------
__global__ void __launch_bounds__(NTH, 2)
pair_gemm_v7(const float* __restrict__ features,
             const float* __restrict__ b_pair,
             const int*   __restrict__ NAS)
{
    const int p  = blockIdx.z;
    const int fi = c_PI[p], fj = c_PJ[p];
    if (((fi < 2) ? 1 : NAS[fi]) * ((fj < 2) ? 1 : NAS[fj]) == 0) return;

    extern __shared__ __align__(16) float sm[];
    float* As = sm;                      // 2 x A_ST
    float* Bs = sm + 2 * A_ST;           // 2 x B_ST
    const uint32_t sB = smem_u32(Bs);

    const int tid  = threadIdx.x;
    const int warp = tid >> 5;
    const int lane = tid & 31;
    const int lt   = lane & 3, lg = lane >> 2;
    const int wm   = warp & 1;
    const int wn   = warp >> 1;
    const int tok0 = blockIdx.x * BM;
    const int n0   = blockIdx.y * BN;

    // per-lane ldmatrix bases
    const int a_row = wm * 64 + ((lane >> 3) & 1) * 8 + (lane & 7);
    const int a_col = ((lane >> 4) & 1) * 4;
    const uint32_t aLane = smem_u32(As) + (uint32_t)((a_row * LDA + a_col) * 4);
    const int b_row = (lane & 7) + ((lane >> 4) & 1) * 8;
    const int b_col = ((lane >> 3) & 1) * 4;
    const uint32_t bLane = sB + (uint32_t)(((wn * 32 + b_row) * LDB + b_col) * 4);

    const float* featI = features + ((size_t)fi * TOKENS + tok0) * EMBED;
    const float* featJ = features + ((size_t)fj * TOKENS + tok0) * EMBED;
    const float* WpT   = g_WpT + ((size_t)p * EMBED + n0) * KPAIR;

    const int NC = KPAIR / BK;   // 16

    // ---- prologue: stage 0 ----
    #pragma unroll
    for (int i = 0; i < 4; i++) {                 // A: 128 rows x 8 float4
        int q = tid + i * NTH, row = q >> 3, cc = q & 7;
        float4 v = *(const float4*)(featI + (size_t)row * EMBED + cc * 4);
        CVT4(As + row * LDA + cc * 4, v);
    }
    #pragma unroll
    for (int i = 0; i < 4; i++) {                 // BT: 128 n-rows x 8 float4
        int q = tid + i * NTH, row = q >> 3, cc = q & 7;
        CP16(sB + (row * LDB + cc * 4) * 4, WpT + (size_t)row * KPAIR + cc * 4);
    }
    CP_COMMIT();
    CP_WAIT0();
    __syncthreads();

    float c[4][4][4];
    #pragma unroll
    for (int m = 0; m < 4; m++)
        #pragma unroll
        for (int n = 0; n < 4; n++)
            #pragma unroll
            for (int r = 0; r < 4; r++)
                c[m][n][r] = 0.0f;

    // ---- main loop (ping-pong, unrolled x2 so buffer selects are static) ----
    #pragma unroll 2
    for (int t = 0; t < NC; t++) {
        float4 aR[4];
        const bool haveN = (t + 1 < NC);
        if (haveN) {
            const int k0 = (t + 1) * BK;          // BK=32 divides EMBED: no straddle
            const float* Asrc = (k0 < EMBED) ? (featI + k0) : (featJ + (k0 - EMBED));
            #pragma unroll
            for (int i = 0; i < 4; i++) {
                int q = tid + i * NTH, row = q >> 3, cc = q & 7;
                aR[i] = *(const float4*)(Asrc + (size_t)row * EMBED + cc * 4);
            }
            const int nb = (t + 1) & 1;
            #pragma unroll
            for (int i = 0; i < 4; i++) {
                int q = tid + i * NTH, row = q >> 3, cc = q & 7;
                CP16(sB + (nb * B_ST + row * LDB + cc * 4) * 4,
                     WpT + (size_t)row * KPAIR + k0 + cc * 4);
            }
            CP_COMMIT();
        }

        const uint32_t aB = aLane + (uint32_t)((t & 1) * A_ST * 4);
        const uint32_t bB = bLane + (uint32_t)((t & 1) * B_ST * 4);
        COMPUTE_STAGE(aB, bB);

        if (haveN) {
            float* Ad = As + ((t + 1) & 1) * A_ST;
            #pragma unroll
            for (int i = 0; i < 4; i++) {
                int q = tid + i * NTH, row = q >> 3, cc = q & 7;
                CVT4(Ad + row * LDA + cc * 4, aR[i]);
            }
        }
        CP_WAIT0();
        __syncthreads();
    }

    // ---- epilogue: stage C via smem halves; bias + tanh + tf32-RN; write g_H ----
    float*       Hout = g_H    + ((size_t)p * TOKENS + tok0) * EMBED + n0;
    const float* bp   = b_pair + p * EMBED + n0;
    float* Cs = sm;
    #pragma unroll
    for (int half = 0; half < 2; half++) {
        if (wm == half) STORE_C_HALF(Cs);
        __syncthreads();
        #pragma unroll
        for (int i = 0; i < 8; i++) {
            int q = tid + i * NTH, row = q >> 5, c4 = (q & 31) * 4;
            float4 v  = *(float4*)(Cs + row * LDC + c4);
            float4 bb = *(const float4*)(bp + c4);
            float4 o;
            o.x = wmma::__float_to_tf32(tanhf(v.x + bb.x));
            o.y = wmma::__float_to_tf32(tanhf(v.y + bb.y));
            o.z = wmma::__float_to_tf32(tanhf(v.z + bb.z));
            o.w = wmma::__float_to_tf32(tanhf(v.w + bb.w));
            *(float4*)(Hout + (size_t)(half * 64 + row) * EMBED + c4) = o;
        }
        __syncthreads();
    }
}

// ---------------------------------------------------------------------------
// Kernel 2: out = H_flat @ W_final + b_final  (active pairs' K-chunks only)
// ---------------------------------------------------------------------------
__global__ void __launch_bounds__(NTH, 2)
final_gemm_v7(const float* __restrict__ b_final,
              const int*   __restrict__ NAS,
              float*       __restrict__ out)
{
    extern __shared__ __align__(16) float sm[];
    float* As = sm;                       // 2 x A_ST
    float* Bs = sm + 2 * A_ST;            // 2 x B_ST
    int*   s_plist = (int*)(sm + SMEM_FLOATS);   // 16 ints
    const uint32_t sA = smem_u32(As);
    const uint32_t sB = smem_u32(Bs);

    const int tid  = threadIdx.x;
    const int warp = tid >> 5;
    const int lane = tid & 31;
    const int lt   = lane & 3, lg = lane >> 2;
    const int wm   = warp & 1;
    const int wn   = warp >> 1;
    const int tok0 = blockIdx.x * BM;
    const int n0   = blockIdx.y * BN;

    const int a_row = wm * 64 + ((lane >> 3) & 1) * 8 + (lane & 7);
    const int a_col = ((lane >> 4) & 1) * 4;
    const uint32_t aLane = sA + (uint32_t)((a_row * LDA + a_col) * 4);
    const int b_row = (lane & 7) + ((lane >> 4) & 1) * 8;
    const int b_col = ((lane >> 3) & 1) * 4;
    const uint32_t bLane = sB + (uint32_t)(((wn * 32 + b_row) * LDB + b_col) * 4);

    if (tid == 0) {
        int nas_eff[6];
        #pragma unroll
        for (int f = 0; f < 6; f++) nas_eff[f] = (f < 2) ? 1 : NAS[f];
        int np = 0;
        #pragma unroll
        for (int p = 0; p < PAIRS; p++)
            if (nas_eff[c_PI[p]] * nas_eff[c_PJ[p]] != 0) s_plist[np++] = p;
        s_plist[15] = np;
    }
    __syncthreads();
    const int NC = s_plist[15] * (EMBED / BK);   // np * 8

    const float* WfT = g_WfT + (size_t)n0 * KFINAL;

    #define ISSUE_STAGE(t_, s_)                                                        \
        do {                                                                           \
            const int _p    = s_plist[(t_) >> 3];                                      \
            const int _kg   = _p * EMBED + ((t_) & 7) * BK;                            \
            const float* _Asrc = g_H + ((size_t)_p * TOKENS + tok0) * EMBED            \
                                 + (((t_) & 7) * BK);                                  \
            _Pragma("unroll")                                                          \
            for (int i = 0; i < 4; i++) {                                              \
                int q = tid + i * NTH, row = q >> 3, cc = q & 7;                       \
                CP16(sA + ((s_) * A_ST + row * LDA + cc * 4) * 4,                      \
                     _Asrc + (size_t)row * EMBED + cc * 4);                            \
            }                                                                          \
            _Pragma("unroll")                                                          \
            for (int i = 0; i < 4; i++) {                                              \
                int q = tid + i * NTH, row = q >> 3, cc = q & 7;                       \
                CP16(sB + ((s_) * B_ST + row * LDB + cc * 4) * 4,                      \
                     WfT + (size_t)row * KFINAL + _kg + cc * 4);                       \
            }                                                                          \
            CP_COMMIT();                                                               \
        } while (0)

    // ---- prologue ----
    ISSUE_STAGE(0, 0);
    CP_WAIT0();
    __syncthreads();

    float c[4][4][4];
    #pragma unroll
    for (int m = 0; m < 4; m++)
        #pragma unroll
        for (int n = 0; n < 4; n++)
            #pragma unroll
            for (int r = 0; r < 4; r++)
                c[m][n][r] = 0.0f;

    // ---- main loop (ping-pong, unrolled x2) ----
    #pragma unroll 2
    for (int t = 0; t < NC; t++) {
        if (t + 1 < NC)
            ISSUE_STAGE(t + 1, (t + 1) & 1);

        const uint32_t aB = aLane + (uint32_t)((t & 1) * A_ST * 4);
        const uint32_t bB = bLane + (uint32_t)((t & 1) * B_ST * 4);
        COMPUTE_STAGE(aB, bB);

        CP_WAIT0();
        __syncthreads();
    }

    // ---- epilogue: bias only ----
    float*       Optr = out     + (size_t)tok0 * EMBED + n0;
    const float* bf_  = b_final + n0;
    float* Cs = sm;
    #pragma unroll
    for (int half = 0; half < 2; half++) {
        if (wm == half) STORE_C_HALF(Cs);
        __syncthreads();
        #pragma unroll
        for (int i = 0; i < 8; i++) {
            int q = tid + i * NTH, row = q >> 5, c4 = (q & 31) * 4;
            float4 v  = *(float4*)(Cs + row * LDC + c4);
            float4 bb = *(const float4*)(bf_ + c4);
            float4 o;
            o.x = v.x + bb.x;
            o.y = v.y + bb.y;
            o.z = v.z + bb.z;
            o.w = v.w + bb.w;
            *(float4*)(Optr + (size_t)(half * 64 + row) * EMBED + c4) = o;
        }
        __syncthreads();
    }
    #undef ISSUE_STAGE
}

// ---------------------------------------------------------------------------
extern "C" void kernel_launch(void* const* d_in, const int* in_sizes, int n_in,
                              void* d_out, int out_size)
{
    const float* features = (const float*)d_in[0];
    const float* W_pair   = (const float*)d_in[1];
    const float* b_pair   = (const float*)d_in[2];
    const float* W_final  = (const float*)d_in[3];
    const float* b_final  = (const float*)d_in[4];
    const int*   NAS      = (const int*)  d_in[5];
    float*       out      = (float*)d_out;

    cudaFuncSetAttribute(pair_gemm_v7,  cudaFuncAttributeMaxDynamicSharedMemorySize,
                         SMEM_BYTES);
    cudaFuncSetAttribute(final_gemm_v7, cudaFuncAttributeMaxDynamicSharedMemorySize,
                         SMEM_BYTES);

    dim3 tgrid(KFINAL / 32, EMBED / 32, PAIRS + 1);   // 120 x 8 x 16
    transpose_round<<<tgrid, NTH>>>(W_pair, W_final, NAS);

    dim3 block(NTH);
    dim3 grid1(TOKENS / BM, EMBED / BN, PAIRS);   // 128 x 2 x 15
    pair_gemm_v7<<<grid1, block, SMEM_BYTES>>>(features, b_pair, NAS);

    dim3 grid2(TOKENS / BM, EMBED / BN);          // 128 x 2
    final_gemm_v7<<<grid2, block, SMEM_BYTES>>>(b_final, NAS, out);
}

// round 16
// speedup vs baseline: 1.0284x; 1.0284x over previous
#include <cuda_runtime.h>
#include <mma.h>
#include <math.h>
#include <stdint.h>

using namespace nvcuda;

#define EMBED   256
#define PAIRS   15
#define TOKENS  16384            // 32 * 512
#define KPAIR   512              // 2 * EMBED
#define KFINAL  3840             // 15 * 256

#define BM 128
#define BN 128
#define BK 32
#define LDA 36                   // 32 + 4 pad floats (144B rows: conflict-free ldmatrix)
#define LDB 136                  // 128 + 8 pad floats (544B rows: conflict-free B LDS, 136%32==8)
#define LDC 136
#define NTH 256

#define A_ST (BM * LDA)          // 4608 floats / stage
#define B_ST (BK * LDB)          // 4352 floats / stage
#define SMEM_FLOATS (2 * A_ST + 2 * B_ST)   // 17920 fl = 71680 B
#define SMEM_BYTES  (SMEM_FLOATS * 4 + 64)  // + s_plist area

// ---- global scratch (allocation-free) ----
__device__ float g_H [(size_t)PAIRS * TOKENS * EMBED];   // tanh outputs, tf32-RN-rounded
__device__ float g_Wp[(size_t)PAIRS * KPAIR * EMBED];    // W_pair, tf32-RN-rounded
__device__ float g_Wf[(size_t)KFINAL * EMBED];           // W_final, tf32-RN-rounded

__constant__ int c_PI[PAIRS] = {0,0,0,0,0,1,1,1,1,2,2,2,3,3,4};
__constant__ int c_PJ[PAIRS] = {1,2,3,4,5,2,3,4,5,3,4,5,4,5,5};

__device__ __forceinline__ uint32_t smem_u32(const void* p) {
    uint32_t a;
    asm("{ .reg .u64 t; cvta.to.shared.u64 t, %1; cvt.u32.u64 %0, t; }" : "=r"(a) : "l"(p));
    return a;
}
#define CP16(dst, src) \
    asm volatile("cp.async.cg.shared.global [%0], [%1], 16;" :: "r"(dst), "l"(src) : "memory")
#define CP_COMMIT()  asm volatile("cp.async.commit_group;" ::: "memory")
#define CP_WAIT0()   asm volatile("cp.async.wait_group 0;" ::: "memory")

#define CVT4(dst, v)                                   \
    do {                                               \
        (dst)[0] = wmma::__float_to_tf32((v).x);       \
        (dst)[1] = wmma::__float_to_tf32((v).y);       \
        (dst)[2] = wmma::__float_to_tf32((v).z);       \
        (dst)[3] = wmma::__float_to_tf32((v).w);       \
    } while (0)

#define RN4(v)                                         \
    do {                                               \
        (v).x = wmma::__float_to_tf32((v).x);          \
        (v).y = wmma::__float_to_tf32((v).y);          \
        (v).z = wmma::__float_to_tf32((v).z);          \
        (v).w = wmma::__float_to_tf32((v).w);          \
    } while (0)

// ---------------------------------------------------------------------------
// Pre-pass: tf32-RN-round weights. z<15: one W_pair pair (skipped when the
// pair is NAS-inactive; its g_Wp region is never read). z==15: W_final.
// ILP-4: each thread moves 4 independent float4s per iteration (MLP>=4).
// grid = (32, 1, 16).
// ---------------------------------------------------------------------------
__global__ void __launch_bounds__(NTH)
round_weights(const float* __restrict__ Wp, const float* __restrict__ Wf,
              const int* __restrict__ NAS)
{
    const int z = blockIdx.z;
    const float4* src;
    float4*       dst;
    int n4;
    if (z < PAIRS) {
        const int fi = c_PI[z], fj = c_PJ[z];
        if (((fi < 2) ? 1 : NAS[fi]) * ((fj < 2) ? 1 : NAS[fj]) == 0) return;
        src = (const float4*)(Wp   + (size_t)z * KPAIR * EMBED);
        dst = (float4*)      (g_Wp + (size_t)z * KPAIR * EMBED);
        n4  = KPAIR * EMBED / 4;     // 32768 -> exactly one iteration
    } else {
        src = (const float4*)Wf;
        dst = (float4*)g_Wf;
        n4  = KFINAL * EMBED / 4;    // 245760
    }
    const int stride = gridDim.x * NTH * 4;
    for (int i = (blockIdx.x * NTH + threadIdx.x) * 4; i < n4; i += stride) {
        float4 v0 = src[i + 0];
        float4 v1 = src[i + 1];
        float4 v2 = src[i + 2];
        float4 v3 = src[i + 3];
        RN4(v0); RN4(v1); RN4(v2); RN4(v3);
        dst[i + 0] = v0;
        dst[i + 1] = v1;
        dst[i + 2] = v2;
        dst[i + 3] = v3;
    }
}

// ---------------------------------------------------------------------------
// Warp-tile compute: 64x32 per warp via ldmatrix + mma.sync.m16n8k8 tf32.
// ---------------------------------------------------------------------------
#define COMPUTE_STAGE(aBaseU32, bBaseF)                                                   \
    do {                                                                                  \
        _Pragma("unroll")                                                                 \
        for (int kk8 = 0; kk8 < 4; kk8++) {                                               \
            const int kk = kk8 * 8;                                                       \
            uint32_t a[4][4];                                                             \
            _Pragma("unroll")                                                             \
            for (int m = 0; m < 4; m++) {                                                 \
                uint32_t ad = (aBaseU32) + (uint32_t)((m * 16 * LDA + kk) * 4);           \
                asm volatile(                                                             \
                    "ldmatrix.sync.aligned.m8n8.x4.shared.b16 {%0,%1,%2,%3}, [%4];"       \
                    : "=r"(a[m][0]), "=r"(a[m][1]), "=r"(a[m][2]), "=r"(a[m][3])          \
                    : "r"(ad));                                                           \
            }                                                                             \
            _Pragma("unroll")                                                             \
            for (int n = 0; n < 4; n++) {                                                 \
                const float* bp = (bBaseF) + kk * LDB + n * 8;                            \
                uint32_t b0 = __float_as_uint(bp[0]);                                     \
                uint32_t b1 = __float_as_uint(bp[4 * LDB]);                               \
                _Pragma("unroll")                                                         \
                for (int m = 0; m < 4; m++)                                               \
                    asm volatile(                                                         \
                        "mma.sync.aligned.m16n8k8.row.col.f32.tf32.tf32.f32 "             \
                        "{%0,%1,%2,%3}, {%4,%5,%6,%7}, {%8,%9}, {%0,%1,%2,%3};"           \
                        : "+f"(c[m][n][0]), "+f"(c[m][n][1]),                             \
                          "+f"(c[m][n][2]), "+f"(c[m][n][3])                              \
                        : "r"(a[m][0]), "r"(a[m][1]), "r"(a[m][2]), "r"(a[m][3]),         \
                          "r"(b0), "r"(b1));                                              \
            }                                                                             \
        }                                                                                 \
    } while (0)

// Store this warp's 64x32 C tile into Cs (64-row half staging), from c fragments.
#define STORE_C_HALF(Cs_)                                                                 \
    do {                                                                                  \
        _Pragma("unroll")                                                                 \
        for (int m = 0; m < 4; m++) {                                                     \
            _Pragma("unroll")                                                             \
            for (int n = 0; n < 4; n++) {                                                 \
                int r0  = m * 16 + lg;                                                    \
                int col = wn * 32 + n * 8 + 2 * lt;                                       \
                *(float2*)((Cs_) + r0 * LDC + col)       = make_float2(c[m][n][0], c[m][n][1]); \
                *(float2*)((Cs_) + (r0 + 8) * LDC + col) = make_float2(c[m][n][2], c[m][n][3]); \
            }                                                                             \
        }                                                                                 \
    } while (0)

// ---------------------------------------------------------------------------
// Kernel 1: H[p] = tf32rn( tanh(concat(F_i,F_j) @ W_pair[p] + b_pair[p]) )
// ---------------------------------------------------------------------------
__global__ void __launch_bounds__(NTH, 2)
pair_gemm_v8(const float* __restrict__ features,
             const float* __restrict__ b_pair,
             const int*   __restrict__ NAS)
{
    const int p  = blockIdx.z;
    const int fi = c_PI[p], fj = c_PJ[p];
    if (((fi < 2) ? 1 : NAS[fi]) * ((fj < 2) ? 1 : NAS[fj]) == 0) return;

    extern __shared__ __align__(16) float sm[];
    float* As = sm;                      // 2 x A_ST
    float* Bs = sm + 2 * A_ST;           // 2 x B_ST
    const uint32_t sB = smem_u32(Bs);

    const int tid  = threadIdx.x;
    const int warp = tid >> 5;
    const int lane = tid & 31;
    const int lt   = lane & 3, lg = lane >> 2;
    const int wm   = warp & 1;
    const int wn   = warp >> 1;
    const int tok0 = blockIdx.x * BM;
    const int n0   = blockIdx.y * BN;

    // per-lane operand bases
    const int a_row = wm * 64 + ((lane >> 3) & 1) * 8 + (lane & 7);
    const int a_col = ((lane >> 4) & 1) * 4;
    const uint32_t aLane = smem_u32(As) + (uint32_t)((a_row * LDA + a_col) * 4);
    const float*   bLane = Bs + lt * LDB + wn * 32 + lg;

    const float* featI = features + ((size_t)fi * TOKENS + tok0) * EMBED;
    const float* featJ = features + ((size_t)fj * TOKENS + tok0) * EMBED;
    const float* Wp    = g_Wp + (size_t)p * KPAIR * EMBED + n0;

    const int NC = KPAIR / BK;   // 16

    // ---- prologue: stage 0 ----
    #pragma unroll
    for (int i = 0; i < 4; i++) {                 // A: 128 rows x 8 float4
        int q = tid + i * NTH, row = q >> 3, cc = q & 7;
        float4 v = *(const float4*)(featI + (size_t)row * EMBED + cc * 4);
        CVT4(As + row * LDA + cc * 4, v);
    }
    #pragma unroll
    for (int i = 0; i < 4; i++) {                 // B: 32 rows x 32 float4
        int q = tid + i * NTH, row = q >> 5, cc = q & 31;
        CP16(sB + (row * LDB) * 4 + cc * 16, Wp + (size_t)row * EMBED + cc * 4);
    }
    CP_COMMIT();
    CP_WAIT0();
    __syncthreads();

    float c[4][4][4];
    #pragma unroll
    for (int m = 0; m < 4; m++)
        #pragma unroll
        for (int n = 0; n < 4; n++)
            #pragma unroll
            for (int r = 0; r < 4; r++)
                c[m][n][r] = 0.0f;

    // ---- main loop (ping-pong, unrolled x2 so buffer selects are static) ----
    #pragma unroll 2
    for (int t = 0; t < NC; t++) {
        float4 aR[4];
        const bool haveN = (t + 1 < NC);
        if (haveN) {
            const int k0 = (t + 1) * BK;          // BK=32 divides EMBED: no straddle
            const float* Asrc = (k0 < EMBED) ? (featI + k0) : (featJ + (k0 - EMBED));
            #pragma unroll
            for (int i = 0; i < 4; i++) {
                int q = tid + i * NTH, row = q >> 3, cc = q & 7;
                aR[i] = *(const float4*)(Asrc + (size_t)row * EMBED + cc * 4);
            }
            const int nb = (t + 1) & 1;
            #pragma unroll
            for (int i = 0; i < 4; i++) {
                int q = tid + i * NTH, row = q >> 5, cc = q & 31;
                CP16(sB + (nb * B_ST + row * LDB) * 4 + cc * 16,
                     Wp + (size_t)(k0 + row) * EMBED + cc * 4);
            }
            CP_COMMIT();
        }

        const uint32_t aB = aLane + (uint32_t)((t & 1) * A_ST * 4);
        const float*   bB = bLane + (t & 1) * B_ST;
        COMPUTE_STAGE(aB, bB);

        if (haveN) {
            float* Ad = As + ((t + 1) & 1) * A_ST;
            #pragma unroll
            for (int i = 0; i < 4; i++) {
                int q = tid + i * NTH, row = q >> 3, cc = q & 7;
                CVT4(Ad + row * LDA + cc * 4, aR[i]);
            }
        }
        CP_WAIT0();
        __syncthreads();
    }

    // ---- epilogue: stage C via smem halves; bias + tanh + tf32-RN; write g_H ----
    float*       Hout = g_H    + ((size_t)p * TOKENS + tok0) * EMBED + n0;
    const float* bp   = b_pair + p * EMBED + n0;
    float* Cs = sm;
    #pragma unroll
    for (int half = 0; half < 2; half++) {
        if (wm == half) STORE_C_HALF(Cs);
        __syncthreads();
        #pragma unroll
        for (int i = 0; i < 8; i++) {
            int q = tid + i * NTH, row = q >> 5, c4 = (q & 31) * 4;
            float4 v  = *(float4*)(Cs + row * LDC + c4);
            float4 bb = *(const float4*)(bp + c4);
            float4 o;
            o.x = wmma::__float_to_tf32(tanhf(v.x + bb.x));
            o.y = wmma::__float_to_tf32(tanhf(v.y + bb.y));
            o.z = wmma::__float_to_tf32(tanhf(v.z + bb.z));
            o.w = wmma::__float_to_tf32(tanhf(v.w + bb.w));
            *(float4*)(Hout + (size_t)(half * 64 + row) * EMBED + c4) = o;
        }
        __syncthreads();
    }
}

// ---------------------------------------------------------------------------
// Kernel 2: out = H_flat @ W_final + b_final  (active pairs' K-chunks only)
// plist lives in shared memory (avoids local-memory dynamic indexing).
// ---------------------------------------------------------------------------
__global__ void __launch_bounds__(NTH, 2)
final_gemm_v8(const float* __restrict__ b_final,
              const int*   __restrict__ NAS,
              float*       __restrict__ out)
{
    extern __shared__ __align__(16) float sm[];
    float* As = sm;                       // 2 x A_ST
    float* Bs = sm + 2 * A_ST;            // 2 x B_ST
    int*   s_plist = (int*)(sm + SMEM_FLOATS);   // 16 ints
    const uint32_t sA = smem_u32(As);
    const uint32_t sB = smem_u32(Bs);

    const int tid  = threadIdx.x;
    const int warp = tid >> 5;
    const int lane = tid & 31;
    const int lt   = lane & 3, lg = lane >> 2;
    const int wm   = warp & 1;
    const int wn   = warp >> 1;
    const int tok0 = blockIdx.x * BM;
    const int n0   = blockIdx.y * BN;

    const int a_row = wm * 64 + ((lane >> 3) & 1) * 8 + (lane & 7);
    const int a_col = ((lane >> 4) & 1) * 4;
    const uint32_t aLane = sA + (uint32_t)((a_row * LDA + a_col) * 4);
    const float*   bLane = Bs + lt * LDB + wn * 32 + lg;

    if (tid == 0) {
        int nas_eff[6];
        #pragma unroll
        for (int f = 0; f < 6; f++) nas_eff[f] = (f < 2) ? 1 : NAS[f];
        int np = 0;
        #pragma unroll
        for (int p = 0; p < PAIRS; p++)
            if (nas_eff[c_PI[p]] * nas_eff[c_PJ[p]] != 0) s_plist[np++] = p;
        s_plist[15] = np;
    }
    __syncthreads();
    const int NC = s_plist[15] * (EMBED / BK);   // np * 8

    #define ISSUE_STAGE(t_, s_)                                                        \
        do {                                                                           \
            const int _p    = s_plist[(t_) >> 3];                                      \
            const int _koff = ((t_) & 7) * BK;                                         \
            const float* _Asrc = g_H + ((size_t)_p * TOKENS + tok0) * EMBED + _koff;   \
            const float* _Bsrc = g_Wf + (size_t)(_p * EMBED + _koff) * EMBED + n0;     \
            _Pragma("unroll")                                                          \
            for (int i = 0; i < 4; i++) {                                              \
                int q = tid + i * NTH, row = q >> 3, cc = q & 7;                       \
                CP16(sA + ((s_) * A_ST + row * LDA) * 4 + cc * 16,                     \
                     _Asrc + (size_t)row * EMBED + cc * 4);                            \
            }                                                                          \
            _Pragma("unroll")                                                          \
            for (int i = 0; i < 4; i++) {                                              \
                int q = tid + i * NTH, row = q >> 5, cc = q & 31;                      \
                CP16(sB + ((s_) * B_ST + row * LDB) * 4 + cc * 16,                     \
                     _Bsrc + (size_t)row * EMBED + cc * 4);                            \
            }                                                                          \
            CP_COMMIT();                                                               \
        } while (0)

    // ---- prologue ----
    ISSUE_STAGE(0, 0);
    CP_WAIT0();
    __syncthreads();

    float c[4][4][4];
    #pragma unroll
    for (int m = 0; m < 4; m++)
        #pragma unroll
        for (int n = 0; n < 4; n++)
            #pragma unroll
            for (int r = 0; r < 4; r++)
                c[m][n][r] = 0.0f;

    // ---- main loop (ping-pong, unrolled x2) ----
    #pragma unroll 2
    for (int t = 0; t < NC; t++) {
        if (t + 1 < NC)
            ISSUE_STAGE(t + 1, (t + 1) & 1);

        const uint32_t aB = aLane + (uint32_t)((t & 1) * A_ST * 4);
        const float*   bB = bLane + (t & 1) * B_ST;
        COMPUTE_STAGE(aB, bB);

        CP_WAIT0();
        __syncthreads();
    }

    // ---- epilogue: bias only ----
    float*       Optr = out     + (size_t)tok0 * EMBED + n0;
    const float* bf_  = b_final + n0;
    float* Cs = sm;
    #pragma unroll
    for (int half = 0; half < 2; half++) {
        if (wm == half) STORE_C_HALF(Cs);
        __syncthreads();
        #pragma unroll
        for (int i = 0; i < 8; i++) {
            int q = tid + i * NTH, row = q >> 5, c4 = (q & 31) * 4;
            float4 v  = *(float4*)(Cs + row * LDC + c4);
            float4 bb = *(const float4*)(bf_ + c4);
            float4 o;
            o.x = v.x + bb.x;
            o.y = v.y + bb.y;
            o.z = v.z + bb.z;
            o.w = v.w + bb.w;
            *(float4*)(Optr + (size_t)(half * 64 + row) * EMBED + c4) = o;
        }
        __syncthreads();
    }
    #undef ISSUE_STAGE
}

// ---------------------------------------------------------------------------
extern "C" void kernel_launch(void* const* d_in, const int* in_sizes, int n_in,
                              void* d_out, int out_size)
{
    const float* features = (const float*)d_in[0];
    const float* W_pair   = (const float*)d_in[1];
    const float* b_pair   = (const float*)d_in[2];
    const float* W_final  = (const float*)d_in[3];
    const float* b_final  = (const float*)d_in[4];
    const int*   NAS      = (const int*)  d_in[5];
    float*       out      = (float*)d_out;

    cudaFuncSetAttribute(pair_gemm_v8,  cudaFuncAttributeMaxDynamicSharedMemorySize,
                         SMEM_BYTES);
    cudaFuncSetAttribute(final_gemm_v8, cudaFuncAttributeMaxDynamicSharedMemorySize,
                         SMEM_BYTES);

    dim3 rgrid(32, 1, PAIRS + 1);                 // 32 x 1 x 16
    round_weights<<<rgrid, NTH>>>(W_pair, W_final, NAS);

    dim3 block(NTH);
    dim3 grid1(TOKENS / BM, EMBED / BN, PAIRS);   // 128 x 2 x 15
    pair_gemm_v8<<<grid1, block, SMEM_BYTES>>>(features, b_pair, NAS);

    dim3 grid2(TOKENS / BM, EMBED / BN);          // 128 x 2
    final_gemm_v8<<<grid2, block, SMEM_BYTES>>>(b_final, NAS, out);
}

// round 17
// speedup vs baseline: 1.1097x; 1.0791x over previous
#include <cuda_runtime.h>
#include <mma.h>
#include <math.h>
#include <stdint.h>

using namespace nvcuda;

#define EMBED   256
#define PAIRS   15
#define TOKENS  16384            // 32 * 512
#define KPAIR   512              // 2 * EMBED
#define KFINAL  3840             // 15 * 256

#define BM 128
#define BN 128
#define BK 32
#define LDA 36                   // 32 + 4 pad floats (144B rows: conflict-free ldmatrix)
#define LDB 136                  // 128 + 8 pad floats (544B rows: conflict-free B LDS, 136%32==8)
#define LDC 136
#define NTH 256

#define A_ST (BM * LDA)          // 4608 floats / stage
#define B_ST (BK * LDB)          // 4352 floats / stage
#define SMEM_FLOATS (2 * A_ST + 2 * B_ST)   // 17920 fl = 71680 B
#define SMEM_BYTES  (SMEM_FLOATS * 4 + 64)  // + s_plist area

// float4 counts for the pre-pass
#define N4_WP (PAIRS * KPAIR * EMBED / 4)   // 491520 (32768 = 2^15 per pair)
#define N4_WF (KFINAL * EMBED / 4)          // 245760
#define N4_TOTAL (N4_WP + N4_WF)            // 737280 = 720 * 256 * 4

// ---- global scratch (allocation-free) ----
__device__ float g_H [(size_t)PAIRS * TOKENS * EMBED];   // tanh outputs, tf32-RN-rounded
__device__ float g_Wp[(size_t)PAIRS * KPAIR * EMBED];    // W_pair, tf32-RN-rounded
__device__ float g_Wf[(size_t)KFINAL * EMBED];           // W_final, tf32-RN-rounded

__constant__ int c_PI[PAIRS] = {0,0,0,0,0,1,1,1,1,2,2,2,3,3,4};
__constant__ int c_PJ[PAIRS] = {1,2,3,4,5,2,3,4,5,3,4,5,4,5,5};

__device__ __forceinline__ uint32_t smem_u32(const void* p) {
    uint32_t a;
    asm("{ .reg .u64 t; cvta.to.shared.u64 t, %1; cvt.u32.u64 %0, t; }" : "=r"(a) : "l"(p));
    return a;
}
#define CP16(dst, src) \
    asm volatile("cp.async.cg.shared.global [%0], [%1], 16;" :: "r"(dst), "l"(src) : "memory")
#define CP_COMMIT()  asm volatile("cp.async.commit_group;" ::: "memory")
#define CP_WAIT0()   asm volatile("cp.async.wait_group 0;" ::: "memory")

#define CVT4(dst, v)                                   \
    do {                                               \
        (dst)[0] = wmma::__float_to_tf32((v).x);       \
        (dst)[1] = wmma::__float_to_tf32((v).y);       \
        (dst)[2] = wmma::__float_to_tf32((v).z);       \
        (dst)[3] = wmma::__float_to_tf32((v).w);       \
    } while (0)

#define RN4(v)                                         \
    do {                                               \
        (v).x = wmma::__float_to_tf32((v).x);          \
        (v).y = wmma::__float_to_tf32((v).y);          \
        (v).z = wmma::__float_to_tf32((v).z);          \
        (v).w = wmma::__float_to_tf32((v).w);          \
    } while (0)

// ---------------------------------------------------------------------------
// Pre-pass: tf32-RN-round both weight tensors. Flat balanced indexing (every
// thread handles 4 consecutive float4, exactly one wave, grid exactly sized),
// with inactive W_pair regions skipped (never read downstream).
// grid = 720 blocks x 256 threads.
// ---------------------------------------------------------------------------
__global__ void __launch_bounds__(NTH)
round_weights(const float* __restrict__ Wp, const float* __restrict__ Wf,
              const int* __restrict__ NAS)
{
    const int i0 = (blockIdx.x * NTH + threadIdx.x) * 4;
    const float4* src;
    float4*       dst;
    if (i0 < N4_WP) {
        const int p  = i0 >> 15;            // 32768 float4 per pair, no straddle
        const int fi = c_PI[p], fj = c_PJ[p];
        if (((fi < 2) ? 1 : NAS[fi]) * ((fj < 2) ? 1 : NAS[fj]) == 0) return;
        src = (const float4*)Wp   + i0;
        dst = (float4*)      g_Wp + i0;
    } else {
        src = (const float4*)Wf   + (i0 - N4_WP);
        dst = (float4*)      g_Wf + (i0 - N4_WP);
    }
    float4 v0 = src[0];
    float4 v1 = src[1];
    float4 v2 = src[2];
    float4 v3 = src[3];
    RN4(v0); RN4(v1); RN4(v2); RN4(v3);
    dst[0] = v0;
    dst[1] = v1;
    dst[2] = v2;
    dst[3] = v3;
}

// ---------------------------------------------------------------------------
// Warp-tile compute: 64x32 per warp via ldmatrix + mma.sync.m16n8k8 tf32.
// ---------------------------------------------------------------------------
#define COMPUTE_STAGE(aBaseU32, bBaseF)                                                   \
    do {                                                                                  \
        _Pragma("unroll")                                                                 \
        for (int kk8 = 0; kk8 < 4; kk8++) {                                               \
            const int kk = kk8 * 8;                                                       \
            uint32_t a[4][4];                                                             \
            _Pragma("unroll")                                                             \
            for (int m = 0; m < 4; m++) {                                                 \
                uint32_t ad = (aBaseU32) + (uint32_t)((m * 16 * LDA + kk) * 4);           \
                asm volatile(                                                             \
                    "ldmatrix.sync.aligned.m8n8.x4.shared.b16 {%0,%1,%2,%3}, [%4];"       \
                    : "=r"(a[m][0]), "=r"(a[m][1]), "=r"(a[m][2]), "=r"(a[m][3])          \
                    : "r"(ad));                                                           \
            }                                                                             \
            _Pragma("unroll")                                                             \
            for (int n = 0; n < 4; n++) {                                                 \
                const float* bp = (bBaseF) + kk * LDB + n * 8;                            \
                uint32_t b0 = __float_as_uint(bp[0]);                                     \
                uint32_t b1 = __float_as_uint(bp[4 * LDB]);                               \
                _Pragma("unroll")                                                         \
                for (int m = 0; m < 4; m++)                                               \
                    asm volatile(                                                         \
                        "mma.sync.aligned.m16n8k8.row.col.f32.tf32.tf32.f32 "             \
                        "{%0,%1,%2,%3}, {%4,%5,%6,%7}, {%8,%9}, {%0,%1,%2,%3};"           \
                        : "+f"(c[m][n][0]), "+f"(c[m][n][1]),                             \
                          "+f"(c[m][n][2]), "+f"(c[m][n][3])                              \
                        : "r"(a[m][0]), "r"(a[m][1]), "r"(a[m][2]), "r"(a[m][3]),         \
                          "r"(b0), "r"(b1));                                              \
            }                                                                             \
        }                                                                                 \
    } while (0)

// Store this warp's 64x32 C tile into Cs (64-row half staging), from c fragments.
#define STORE_C_HALF(Cs_)                                                                 \
    do {                                                                                  \
        _Pragma("unroll")                                                                 \
        for (int m = 0; m < 4; m++) {                                                     \
            _Pragma("unroll")                                                             \
            for (int n = 0; n < 4; n++) {                                                 \
                int r0  = m * 16 + lg;                                                    \
                int col = wn * 32 + n * 8 + 2 * lt;                                       \
                *(float2*)((Cs_) + r0 * LDC + col)       = make_float2(c[m][n][0], c[m][n][1]); \
                *(float2*)((Cs_) + (r0 + 8) * LDC + col) = make_float2(c[m][n][2], c[m][n][3]); \
            }                                                                             \
        }                                                                                 \
    } while (0)

// ---------------------------------------------------------------------------
// Kernel 1: H[p] = tf32rn( tanh(concat(F_i,F_j) @ W_pair[p] + b_pair[p]) )
// ---------------------------------------------------------------------------
__global__ void __launch_bounds__(NTH, 2)
pair_gemm_v9(const float* __restrict__ features,
             const float* __restrict__ b_pair,
             const int*   __restrict__ NAS)
{
    const int p  = blockIdx.z;
    const int fi = c_PI[p], fj = c_PJ[p];
    if (((fi < 2) ? 1 : NAS[fi]) * ((fj < 2) ? 1 : NAS[fj]) == 0) return;

    extern __shared__ __align__(16) float sm[];
    float* As = sm;                      // 2 x A_ST
    float* Bs = sm + 2 * A_ST;           // 2 x B_ST
    const uint32_t sB = smem_u32(Bs);

    const int tid  = threadIdx.x;
    const int warp = tid >> 5;
    const int lane = tid & 31;
    const int lt   = lane & 3, lg = lane >> 2;
    const int wm   = warp & 1;
    const int wn   = warp >> 1;
    const int tok0 = blockIdx.x * BM;
    const int n0   = blockIdx.y * BN;

    // per-lane operand bases
    const int a_row = wm * 64 + ((lane >> 3) & 1) * 8 + (lane & 7);
    const int a_col = ((lane >> 4) & 1) * 4;
    const uint32_t aLane = smem_u32(As) + (uint32_t)((a_row * LDA + a_col) * 4);
    const float*   bLane = Bs + lt * LDB + wn * 32 + lg;

    const float* featI = features + ((size_t)fi * TOKENS + tok0) * EMBED;
    const float* featJ = features + ((size_t)fj * TOKENS + tok0) * EMBED;
    const float* Wp    = g_Wp + (size_t)p * KPAIR * EMBED + n0;

    const int NC = KPAIR / BK;   // 16

    // ---- prologue: stage 0 ----
    #pragma unroll
    for (int i = 0; i < 4; i++) {                 // A: 128 rows x 8 float4
        int q = tid + i * NTH, row = q >> 3, cc = q & 7;
        float4 v = *(const float4*)(featI + (size_t)row * EMBED + cc * 4);
        CVT4(As + row * LDA + cc * 4, v);
    }
    #pragma unroll
    for (int i = 0; i < 4; i++) {                 // B: 32 rows x 32 float4
        int q = tid + i * NTH, row = q >> 5, cc = q & 31;
        CP16(sB + (row * LDB) * 4 + cc * 16, Wp + (size_t)row * EMBED + cc * 4);
    }
    CP_COMMIT();
    CP_WAIT0();
    __syncthreads();

    float c[4][4][4];
    #pragma unroll
    for (int m = 0; m < 4; m++)
        #pragma unroll
        for (int n = 0; n < 4; n++)
            #pragma unroll
            for (int r = 0; r < 4; r++)
                c[m][n][r] = 0.0f;

    // ---- main loop (ping-pong, unrolled x2 so buffer selects are static) ----
    #pragma unroll 2
    for (int t = 0; t < NC; t++) {
        float4 aR[4];
        const bool haveN = (t + 1 < NC);
        if (haveN) {
            const int k0 = (t + 1) * BK;          // BK=32 divides EMBED: no straddle
            const float* Asrc = (k0 < EMBED) ? (featI + k0) : (featJ + (k0 - EMBED));
            #pragma unroll
            for (int i = 0; i < 4; i++) {
                int q = tid + i * NTH, row = q >> 3, cc = q & 7;
                aR[i] = *(const float4*)(Asrc + (size_t)row * EMBED + cc * 4);
            }
            const int nb = (t + 1) & 1;
            #pragma unroll
            for (int i = 0; i < 4; i++) {
                int q = tid + i * NTH, row = q >> 5, cc = q & 31;
                CP16(sB + (nb * B_ST + row * LDB) * 4 + cc * 16,
                     Wp + (size_t)(k0 + row) * EMBED + cc * 4);
            }
            CP_COMMIT();
        }

        const uint32_t aB = aLane + (uint32_t)((t & 1) * A_ST * 4);
        const float*   bB = bLane + (t & 1) * B_ST;
        COMPUTE_STAGE(aB, bB);

        if (haveN) {
            float* Ad = As + ((t + 1) & 1) * A_ST;
            #pragma unroll
            for (int i = 0; i < 4; i++) {
                int q = tid + i * NTH, row = q >> 3, cc = q & 7;
                CVT4(Ad + row * LDA + cc * 4, aR[i]);
            }
        }
        CP_WAIT0();
        __syncthreads();
    }

    // ---- epilogue: stage C via smem halves; bias + tanh + tf32-RN; write g_H ----
    float*       Hout = g_H    + ((size_t)p * TOKENS + tok0) * EMBED + n0;
    const float* bp   = b_pair + p * EMBED + n0;
    float* Cs = sm;
    #pragma unroll
    for (int half = 0; half < 2; half++) {
        if (wm == half) STORE_C_HALF(Cs);
        __syncthreads();
        #pragma unroll
        for (int i = 0; i < 8; i++) {
            int q = tid + i * NTH, row = q >> 5, c4 = (q & 31) * 4;
            float4 v  = *(float4*)(Cs + row * LDC + c4);
            float4 bb = *(const float4*)(bp + c4);
            float4 o;
            o.x = wmma::__float_to_tf32(tanhf(v.x + bb.x));
            o.y = wmma::__float_to_tf32(tanhf(v.y + bb.y));
            o.z = wmma::__float_to_tf32(tanhf(v.z + bb.z));
            o.w = wmma::__float_to_tf32(tanhf(v.w + bb.w));
            *(float4*)(Hout + (size_t)(half * 64 + row) * EMBED + c4) = o;
        }
        __syncthreads();
    }
}

// ---------------------------------------------------------------------------
// Kernel 2: out = H_flat @ W_final + b_final  (active pairs' K-chunks only)
// plist lives in shared memory (avoids local-memory dynamic indexing).
// ---------------------------------------------------------------------------
__global__ void __launch_bounds__(NTH, 2)
final_gemm_v9(const float* __restrict__ b_final,
              const int*   __restrict__ NAS,
              float*       __restrict__ out)
{
    extern __shared__ __align__(16) float sm[];
    float* As = sm;                       // 2 x A_ST
    float* Bs = sm + 2 * A_ST;            // 2 x B_ST
    int*   s_plist = (int*)(sm + SMEM_FLOATS);   // 16 ints
    const uint32_t sA = smem_u32(As);
    const uint32_t sB = smem_u32(Bs);

    const int tid  = threadIdx.x;
    const int warp = tid >> 5;
    const int lane = tid & 31;
    const int lt   = lane & 3, lg = lane >> 2;
    const int wm   = warp & 1;
    const int wn   = warp >> 1;
    const int tok0 = blockIdx.x * BM;
    const int n0   = blockIdx.y * BN;

    const int a_row = wm * 64 + ((lane >> 3) & 1) * 8 + (lane & 7);
    const int a_col = ((lane >> 4) & 1) * 4;
    const uint32_t aLane = sA + (uint32_t)((a_row * LDA + a_col) * 4);
    const float*   bLane = Bs + lt * LDB + wn * 32 + lg;

    if (tid == 0) {
        int nas_eff[6];
        #pragma unroll
        for (int f = 0; f < 6; f++) nas_eff[f] = (f < 2) ? 1 : NAS[f];
        int np = 0;
        #pragma unroll
        for (int p = 0; p < PAIRS; p++)
            if (nas_eff[c_PI[p]] * nas_eff[c_PJ[p]] != 0) s_plist[np++] = p;
        s_plist[15] = np;
    }
    __syncthreads();
    const int NC = s_plist[15] * (EMBED / BK);   // np * 8

    #define ISSUE_STAGE(t_, s_)                                                        \
        do {                                                                           \
            const int _p    = s_plist[(t_) >> 3];                                      \
            const int _koff = ((t_) & 7) * BK;                                         \
            const float* _Asrc = g_H + ((size_t)_p * TOKENS + tok0) * EMBED + _koff;   \
            const float* _Bsrc = g_Wf + (size_t)(_p * EMBED + _koff) * EMBED + n0;     \
            _Pragma("unroll")                                                          \
            for (int i = 0; i < 4; i++) {                                              \
                int q = tid + i * NTH, row = q >> 3, cc = q & 7;                       \
                CP16(sA + ((s_) * A_ST + row * LDA) * 4 + cc * 16,                     \
                     _Asrc + (size_t)row * EMBED + cc * 4);                            \
            }                                                                          \
            _Pragma("unroll")                                                          \
            for (int i = 0; i < 4; i++) {                                              \
                int q = tid + i * NTH, row = q >> 5, cc = q & 31;                      \
                CP16(sB + ((s_) * B_ST + row * LDB) * 4 + cc * 16,                     \
                     _Bsrc + (size_t)row * EMBED + cc * 4);                            \
            }                                                                          \
            CP_COMMIT();                                                               \
        } while (0)

    // ---- prologue ----
    ISSUE_STAGE(0, 0);
    CP_WAIT0();
    __syncthreads();

    float c[4][4][4];
    #pragma unroll
    for (int m = 0; m < 4; m++)
        #pragma unroll
        for (int n = 0; n < 4; n++)
            #pragma unroll
            for (int r = 0; r < 4; r++)
                c[m][n][r] = 0.0f;

    // ---- main loop (ping-pong, unrolled x2) ----
    #pragma unroll 2
    for (int t = 0; t < NC; t++) {
        if (t + 1 < NC)
            ISSUE_STAGE(t + 1, (t + 1) & 1);

        const uint32_t aB = aLane + (uint32_t)((t & 1) * A_ST * 4);
        const float*   bB = bLane + (t & 1) * B_ST;
        COMPUTE_STAGE(aB, bB);

        CP_WAIT0();
        __syncthreads();
    }

    // ---- epilogue: bias only ----
    float*       Optr = out     + (size_t)tok0 * EMBED + n0;
    const float* bf_  = b_final + n0;
    float* Cs = sm;
    #pragma unroll
    for (int half = 0; half < 2; half++) {
        if (wm == half) STORE_C_HALF(Cs);
        __syncthreads();
        #pragma unroll
        for (int i = 0; i < 8; i++) {
            int q = tid + i * NTH, row = q >> 5, c4 = (q & 31) * 4;
            float4 v  = *(float4*)(Cs + row * LDC + c4);
            float4 bb = *(const float4*)(bf_ + c4);
            float4 o;
            o.x = v.x + bb.x;
            o.y = v.y + bb.y;
            o.z = v.z + bb.z;
            o.w = v.w + bb.w;
            *(float4*)(Optr + (size_t)(half * 64 + row) * EMBED + c4) = o;
        }
        __syncthreads();
    }
    #undef ISSUE_STAGE
}

// ---------------------------------------------------------------------------
extern "C" void kernel_launch(void* const* d_in, const int* in_sizes, int n_in,
                              void* d_out, int out_size)
{
    const float* features = (const float*)d_in[0];
    const float* W_pair   = (const float*)d_in[1];
    const float* b_pair   = (const float*)d_in[2];
    const float* W_final  = (const float*)d_in[3];
    const float* b_final  = (const float*)d_in[4];
    const int*   NAS      = (const int*)  d_in[5];
    float*       out      = (float*)d_out;

    cudaFuncSetAttribute(pair_gemm_v9,  cudaFuncAttributeMaxDynamicSharedMemorySize,
                         SMEM_BYTES);
    cudaFuncSetAttribute(final_gemm_v9, cudaFuncAttributeMaxDynamicSharedMemorySize,
                         SMEM_BYTES);

    round_weights<<<N4_TOTAL / (NTH * 4), NTH>>>(W_pair, W_final, NAS);  // 720 blocks

    dim3 block(NTH);
    dim3 grid1(TOKENS / BM, EMBED / BN, PAIRS);   // 128 x 2 x 15
    pair_gemm_v9<<<grid1, block, SMEM_BYTES>>>(features, b_pair, NAS);

    dim3 grid2(TOKENS / BM, EMBED / BN);          // 128 x 2
    final_gemm_v9<<<grid2, block, SMEM_BYTES>>>(b_final, NAS, out);
}